// round 2
// baseline (speedup 1.0000x reference)
#include <cuda_runtime.h>
#include <cuda_bf16.h>
#include <math.h>

// ---------------------------------------------------------------------------
// InternVisionLayer: B=16, S=1025, H=1024, NH=16, HD=64, I=4096
// M = B*S = 16400 tokens.
// Pipeline:
//   LN1 -> QKV gemm -> scores gemm -> softmax -> PV gemm -> proj gemm (+ls1 resid)
//   -> LN2 -> fc1 gemm (+gelu) -> fc2 gemm (+ls2 resid)
// ---------------------------------------------------------------------------

#define M_TOK   16400
#define SEQ     1025
#define BATCH   16
#define HID     1024
#define NHEADS  16
#define HDIM    64
#define IMED    4096
#define LDS_SC  1028   // padded row stride for score buffer (16B aligned)

// Scratch (device globals; allocation-free per harness rules)
__device__ float g_xnorm [(size_t)M_TOK * HID];            //  67 MB
__device__ float g_qkv   [(size_t)M_TOK * 3 * HID];        // 201 MB
__device__ float g_scores[(size_t)BATCH * NHEADS * SEQ * LDS_SC]; // ~1.08 GB
__device__ float g_attn  [(size_t)M_TOK * HID];            //  67 MB
__device__ float g_mlp   [(size_t)M_TOK * IMED];           // 269 MB

// ---------------------------------------------------------------------------
// LayerNorm: one block (256 threads) per row of 1024
// ---------------------------------------------------------------------------
__global__ void layernorm_k(const float* __restrict__ x,
                            const float* __restrict__ g,
                            const float* __restrict__ b,
                            float* __restrict__ out) {
    int row = blockIdx.x;
    int t = threadIdx.x;
    const float4* xr = (const float4*)(x + (size_t)row * HID);
    float4 v = xr[t];
    float s  = v.x + v.y + v.z + v.w;
    float ss = v.x*v.x + v.y*v.y + v.z*v.z + v.w*v.w;
    #pragma unroll
    for (int o = 16; o; o >>= 1) {
        s  += __shfl_xor_sync(0xffffffffu, s,  o);
        ss += __shfl_xor_sync(0xffffffffu, ss, o);
    }
    __shared__ float sh[16];
    if ((t & 31) == 0) { sh[t >> 5] = s; sh[8 + (t >> 5)] = ss; }
    __syncthreads();
    s = 0.f; ss = 0.f;
    #pragma unroll
    for (int i = 0; i < 8; i++) { s += sh[i]; ss += sh[8 + i]; }
    float mean = s * (1.0f / HID);
    float var  = ss * (1.0f / HID) - mean * mean;
    float inv  = rsqrtf(var + 1e-5f);
    float4 gv = ((const float4*)g)[t];
    float4 bv = ((const float4*)b)[t];
    float4 o;
    o.x = (v.x - mean) * inv * gv.x + bv.x;
    o.y = (v.y - mean) * inv * gv.y + bv.y;
    o.z = (v.z - mean) * inv * gv.z + bv.z;
    o.w = (v.w - mean) * inv * gv.w + bv.w;
    ((float4*)(out + (size_t)row * HID))[t] = o;
}

// ---------------------------------------------------------------------------
// Generic C = A[M,K] * B[N,K]^T with epilogues. 64x64x16 tile, 4x4 microtile.
// MODE 1: +bias   MODE 2: +bias, gelu   MODE 3: resid + ls*( . + bias )
// ---------------------------------------------------------------------------
template <int MODE>
__global__ void gemm_nt(const float* __restrict__ A,
                        const float* __restrict__ Bw,
                        const float* __restrict__ bias,
                        const float* __restrict__ ls,
                        const float* __restrict__ resid,
                        float* __restrict__ C,
                        int M, int N, int K) {
    __shared__ float As[16][68];
    __shared__ float Bs[16][68];
    int tid = threadIdx.x;
    int tx = tid & 15, ty = tid >> 4;
    int m0 = blockIdx.y * 64, n0 = blockIdx.x * 64;

    int lr = tid >> 2;          // 0..63
    int lk = (tid & 3) * 4;     // 0,4,8,12
    bool aok = (m0 + lr) < M;
    bool bok = (n0 + lr) < N;
    const float* Ap = A  + (size_t)(m0 + lr) * K + lk;
    const float* Bp = Bw + (size_t)(n0 + lr) * K + lk;

    float acc[4][4] = {};
    const float4 zf4 = make_float4(0.f, 0.f, 0.f, 0.f);

    for (int k0 = 0; k0 < K; k0 += 16) {
        float4 av = aok ? *(const float4*)(Ap + k0) : zf4;
        float4 bv = bok ? *(const float4*)(Bp + k0) : zf4;
        __syncthreads();
        As[lk + 0][lr] = av.x; As[lk + 1][lr] = av.y;
        As[lk + 2][lr] = av.z; As[lk + 3][lr] = av.w;
        Bs[lk + 0][lr] = bv.x; Bs[lk + 1][lr] = bv.y;
        Bs[lk + 2][lr] = bv.z; Bs[lk + 3][lr] = bv.w;
        __syncthreads();
        #pragma unroll
        for (int kk = 0; kk < 16; kk++) {
            float4 a = *(const float4*)&As[kk][ty * 4];
            float4 b = *(const float4*)&Bs[kk][tx * 4];
            acc[0][0] += a.x*b.x; acc[0][1] += a.x*b.y; acc[0][2] += a.x*b.z; acc[0][3] += a.x*b.w;
            acc[1][0] += a.y*b.x; acc[1][1] += a.y*b.y; acc[1][2] += a.y*b.z; acc[1][3] += a.y*b.w;
            acc[2][0] += a.z*b.x; acc[2][1] += a.z*b.y; acc[2][2] += a.z*b.z; acc[2][3] += a.z*b.w;
            acc[3][0] += a.w*b.x; acc[3][1] += a.w*b.y; acc[3][2] += a.w*b.z; acc[3][3] += a.w*b.w;
        }
    }

    #pragma unroll
    for (int i = 0; i < 4; i++) {
        int row = m0 + ty * 4 + i;
        if (row >= M) continue;
        #pragma unroll
        for (int j = 0; j < 4; j++) {
            int col = n0 + tx * 4 + j;
            if (col >= N) continue;
            float v = acc[i][j];
            size_t idx = (size_t)row * N + col;
            if (MODE == 1) {
                v += bias[col];
            } else if (MODE == 2) {
                v += bias[col];
                v = 0.5f * v * (1.0f + erff(v * 0.70710678118654752f));
            } else if (MODE == 3) {
                v = resid[idx] + ls[col] * (v + bias[col]);
            }
            C[idx] = v;
        }
    }
}

// ---------------------------------------------------------------------------
// Attention scores: per (b,h): S[q,k] = scale * Q[q,:]·K[k,:], HD=64
// ---------------------------------------------------------------------------
__global__ void attn_scores_k(const float* __restrict__ qkv,
                              float* __restrict__ scores) {
    __shared__ float As[16][68];
    __shared__ float Bs[16][68];
    int tid = threadIdx.x;
    int tx = tid & 15, ty = tid >> 4;
    int z = blockIdx.z, b = z >> 4, h = z & 15;
    int q0 = blockIdx.y * 64, n0 = blockIdx.x * 64;

    const float* Q  = qkv + (size_t)b * SEQ * (3 * HID) + h * HDIM;
    const float* Kp = qkv + (size_t)b * SEQ * (3 * HID) + HID + h * HDIM;

    int lr = tid >> 2;
    int lk = (tid & 3) * 4;
    bool aok = (q0 + lr) < SEQ;
    bool bok = (n0 + lr) < SEQ;
    float acc[4][4] = {};
    const float4 zf4 = make_float4(0.f, 0.f, 0.f, 0.f);

    #pragma unroll
    for (int k0 = 0; k0 < HDIM; k0 += 16) {
        float4 av = aok ? *(const float4*)(Q  + (size_t)(q0 + lr) * (3 * HID) + k0 + lk) : zf4;
        float4 bv = bok ? *(const float4*)(Kp + (size_t)(n0 + lr) * (3 * HID) + k0 + lk) : zf4;
        __syncthreads();
        As[lk + 0][lr] = av.x; As[lk + 1][lr] = av.y;
        As[lk + 2][lr] = av.z; As[lk + 3][lr] = av.w;
        Bs[lk + 0][lr] = bv.x; Bs[lk + 1][lr] = bv.y;
        Bs[lk + 2][lr] = bv.z; Bs[lk + 3][lr] = bv.w;
        __syncthreads();
        #pragma unroll
        for (int kk = 0; kk < 16; kk++) {
            float4 a = *(const float4*)&As[kk][ty * 4];
            float4 b2 = *(const float4*)&Bs[kk][tx * 4];
            acc[0][0] += a.x*b2.x; acc[0][1] += a.x*b2.y; acc[0][2] += a.x*b2.z; acc[0][3] += a.x*b2.w;
            acc[1][0] += a.y*b2.x; acc[1][1] += a.y*b2.y; acc[1][2] += a.y*b2.z; acc[1][3] += a.y*b2.w;
            acc[2][0] += a.z*b2.x; acc[2][1] += a.z*b2.y; acc[2][2] += a.z*b2.z; acc[2][3] += a.z*b2.w;
            acc[3][0] += a.w*b2.x; acc[3][1] += a.w*b2.y; acc[3][2] += a.w*b2.z; acc[3][3] += a.w*b2.w;
        }
    }

    float* Cb = scores + (size_t)z * SEQ * LDS_SC;
    #pragma unroll
    for (int i = 0; i < 4; i++) {
        int row = q0 + ty * 4 + i;
        if (row >= SEQ) continue;
        #pragma unroll
        for (int j = 0; j < 4; j++) {
            int col = n0 + tx * 4 + j;
            if (col >= SEQ) continue;
            Cb[(size_t)row * LDS_SC + col] = acc[i][j] * 0.125f;  // HD^-0.5
        }
    }
}

// ---------------------------------------------------------------------------
// Softmax over rows of length 1025 (ld = 1028; zero the 3 pad slots).
// ---------------------------------------------------------------------------
__global__ void softmax_k(float* __restrict__ scores) {
    size_t row = blockIdx.x;
    float* p = scores + row * LDS_SC;
    int t = threadIdx.x;

    float vals[5];
    int cnt = 0;
    float mx = -1e30f;
    for (int i = t; i < SEQ; i += 256) {
        float v = p[i];
        vals[cnt++] = v;
        mx = fmaxf(mx, v);
    }
    __shared__ float sh[8];
    #pragma unroll
    for (int o = 16; o; o >>= 1) mx = fmaxf(mx, __shfl_xor_sync(0xffffffffu, mx, o));
    if ((t & 31) == 0) sh[t >> 5] = mx;
    __syncthreads();
    mx = sh[0];
    #pragma unroll
    for (int i = 1; i < 8; i++) mx = fmaxf(mx, sh[i]);
    __syncthreads();

    float sum = 0.f;
    for (int j = 0; j < cnt; j++) { vals[j] = __expf(vals[j] - mx); sum += vals[j]; }
    #pragma unroll
    for (int o = 16; o; o >>= 1) sum += __shfl_xor_sync(0xffffffffu, sum, o);
    if ((t & 31) == 0) sh[t >> 5] = sum;
    __syncthreads();
    sum = 0.f;
    #pragma unroll
    for (int i = 0; i < 8; i++) sum += sh[i];
    float inv = 1.0f / sum;

    cnt = 0;
    for (int i = t; i < SEQ; i += 256) p[i] = vals[cnt++] * inv;
    if (t < 3) p[SEQ + t] = 0.f;  // zero padding so PV float4 loads see zeros
}

// ---------------------------------------------------------------------------
// PV: per (b,h): O[q,d] = sum_k P[q,k] * V[k,d]  (K-dim = 1025, N = 64)
// ---------------------------------------------------------------------------
__global__ void attn_pv_k(const float* __restrict__ scores,
                          const float* __restrict__ qkv,
                          float* __restrict__ out) {
    __shared__ float As[16][68];
    __shared__ float Bs[16][68];
    int tid = threadIdx.x;
    int tx = tid & 15, ty = tid >> 4;
    int z = blockIdx.z, b = z >> 4, h = z & 15;
    int q0 = blockIdx.y * 64;

    const float* P = scores + (size_t)z * SEQ * LDS_SC;
    const float* V = qkv + (size_t)b * SEQ * (3 * HID) + 2 * HID + h * HDIM;
    float* Cb = out + (size_t)b * SEQ * HID + h * HDIM;

    int alr = tid >> 2;
    int alk = (tid & 3) * 4;
    int br = tid >> 4;          // 0..15 (k row within tile)
    int bc = (tid & 15) * 4;    // 0..60 (col)
    bool arow = (q0 + alr) < SEQ;
    float acc[4][4] = {};
    const float4 zf4 = make_float4(0.f, 0.f, 0.f, 0.f);

    for (int k0 = 0; k0 < SEQ; k0 += 16) {
        bool aok = arow && (k0 + alk) < SEQ;  // pad cols 1025..1027 are zero
        float4 av = aok ? *(const float4*)(P + (size_t)(q0 + alr) * LDS_SC + k0 + alk) : zf4;
        int kr = k0 + br;
        float4 bv = (kr < SEQ) ? *(const float4*)(V + (size_t)kr * (3 * HID) + bc) : zf4;
        __syncthreads();
        As[alk + 0][alr] = av.x; As[alk + 1][alr] = av.y;
        As[alk + 2][alr] = av.z; As[alk + 3][alr] = av.w;
        *(float4*)&Bs[br][bc] = bv;
        __syncthreads();
        #pragma unroll
        for (int kk = 0; kk < 16; kk++) {
            float4 a = *(const float4*)&As[kk][ty * 4];
            float4 b2 = *(const float4*)&Bs[kk][tx * 4];
            acc[0][0] += a.x*b2.x; acc[0][1] += a.x*b2.y; acc[0][2] += a.x*b2.z; acc[0][3] += a.x*b2.w;
            acc[1][0] += a.y*b2.x; acc[1][1] += a.y*b2.y; acc[1][2] += a.y*b2.z; acc[1][3] += a.y*b2.w;
            acc[2][0] += a.z*b2.x; acc[2][1] += a.z*b2.y; acc[2][2] += a.z*b2.z; acc[2][3] += a.z*b2.w;
            acc[3][0] += a.w*b2.x; acc[3][1] += a.w*b2.y; acc[3][2] += a.w*b2.z; acc[3][3] += a.w*b2.w;
        }
    }

    #pragma unroll
    for (int i = 0; i < 4; i++) {
        int row = q0 + ty * 4 + i;
        if (row >= SEQ) continue;
        #pragma unroll
        for (int j = 0; j < 4; j++) {
            int col = tx * 4 + j;  // < 64 always
            Cb[(size_t)row * HID + col] = acc[i][j];
        }
    }
}

// ---------------------------------------------------------------------------
extern "C" void kernel_launch(void* const* d_in, const int* in_sizes, int n_in,
                              void* d_out, int out_size) {
    const float* hidden = (const float*)d_in[0];
    const float* n1g    = (const float*)d_in[1];
    const float* n1b    = (const float*)d_in[2];
    const float* qkvw   = (const float*)d_in[3];
    const float* qkvb   = (const float*)d_in[4];
    const float* projw  = (const float*)d_in[5];
    const float* projb  = (const float*)d_in[6];
    const float* ls1    = (const float*)d_in[7];
    const float* n2g    = (const float*)d_in[8];
    const float* n2b    = (const float*)d_in[9];
    const float* fc1w   = (const float*)d_in[10];
    const float* fc1b   = (const float*)d_in[11];
    const float* fc2w   = (const float*)d_in[12];
    const float* fc2b   = (const float*)d_in[13];
    const float* ls2    = (const float*)d_in[14];
    float* out = (float*)d_out;

    float *xnorm, *qkv, *scores, *attn, *mlp;
    cudaGetSymbolAddress((void**)&xnorm,  g_xnorm);
    cudaGetSymbolAddress((void**)&qkv,    g_qkv);
    cudaGetSymbolAddress((void**)&scores, g_scores);
    cudaGetSymbolAddress((void**)&attn,   g_attn);
    cudaGetSymbolAddress((void**)&mlp,    g_mlp);

    const int MT = (M_TOK + 63) / 64;  // 257

    // 1. LN1
    layernorm_k<<<M_TOK, 256>>>(hidden, n1g, n1b, xnorm);
    // 2. QKV: [M,1024] x [3072,1024]^T
    gemm_nt<1><<<dim3(3 * HID / 64, MT), 256>>>(xnorm, qkvw, qkvb, nullptr, nullptr,
                                                qkv, M_TOK, 3 * HID, HID);
    // 3. scores
    attn_scores_k<<<dim3(17, 17, BATCH * NHEADS), 256>>>(qkv, scores);
    // 4. softmax
    softmax_k<<<BATCH * NHEADS * SEQ, 256>>>(scores);
    // 5. P @ V
    attn_pv_k<<<dim3(1, 17, BATCH * NHEADS), 256>>>(scores, qkv, attn);
    // 6. proj + ls1 residual -> d_out
    gemm_nt<3><<<dim3(HID / 64, MT), 256>>>(attn, projw, projb, ls1, hidden,
                                            out, M_TOK, HID, HID);
    // 7. LN2
    layernorm_k<<<M_TOK, 256>>>(out, n2g, n2b, xnorm);
    // 8. fc1 + gelu
    gemm_nt<2><<<dim3(IMED / 64, MT), 256>>>(xnorm, fc1w, fc1b, nullptr, nullptr,
                                             mlp, M_TOK, IMED, HID);
    // 9. fc2 + ls2 residual (in place on d_out)
    gemm_nt<3><<<dim3(HID / 64, MT), 256>>>(mlp, fc2w, fc2b, ls2, out,
                                            out, M_TOK, HID, IMED);
}

// round 3
// speedup vs baseline: 3.0321x; 3.0321x over previous
#include <cuda_runtime.h>
#include <cuda_bf16.h>
#include <math.h>

// ---------------------------------------------------------------------------
// InternVisionLayer: B=16, S=1025, H=1024, NH=16, HD=64, I=4096, M = 16400
// R2: all GEMMs on tensor cores via mma.sync m16n8k8 TF32 (fp32 accum),
//     double-buffered cp.async pipelines, fused epilogues.
// ---------------------------------------------------------------------------

#define M_TOK   16400
#define SEQ     1025
#define BATCH   16
#define HID     1024
#define NHEADS  16
#define HDIM    64
#define IMED    4096
#define LDS_SC  1028   // padded row stride for score buffer (16B aligned)

__device__ float g_xnorm [(size_t)M_TOK * HID];
__device__ float g_qkv   [(size_t)M_TOK * 3 * HID];
__device__ float g_scores[(size_t)BATCH * NHEADS * SEQ * LDS_SC];
__device__ float g_attn  [(size_t)M_TOK * HID];
__device__ float g_mlp   [(size_t)M_TOK * IMED];

// ---------------------------------------------------------------------------
// helpers
// ---------------------------------------------------------------------------
__device__ __forceinline__ unsigned f2tf(float x) {
    unsigned u;
    asm("cvt.rna.tf32.f32 %0, %1;" : "=r"(u) : "f"(x));
    return u;
}

__device__ __forceinline__ void mma_tf32(float* d, const unsigned* a, const unsigned* b) {
    asm volatile(
        "mma.sync.aligned.m16n8k8.row.col.f32.tf32.tf32.f32 "
        "{%0,%1,%2,%3}, {%4,%5,%6,%7}, {%8,%9}, {%0,%1,%2,%3};"
        : "+f"(d[0]), "+f"(d[1]), "+f"(d[2]), "+f"(d[3])
        : "r"(a[0]), "r"(a[1]), "r"(a[2]), "r"(a[3]), "r"(b[0]), "r"(b[1]));
}

__device__ __forceinline__ void cp16(void* sdst, const void* gsrc, bool pred) {
    unsigned sa = (unsigned)__cvta_generic_to_shared(sdst);
    int sz = pred ? 16 : 0;
    asm volatile("cp.async.cg.shared.global [%0], [%1], 16, %2;\n"
                 :: "r"(sa), "l"(gsrc), "r"(sz));
}
__device__ __forceinline__ void cp_commit() { asm volatile("cp.async.commit_group;"); }

__device__ __forceinline__ float gelu_f(float v) {
    return 0.5f * v * (1.0f + erff(v * 0.70710678118654752f));
}

// ---------------------------------------------------------------------------
// LayerNorm: one block (256 threads) per row of 1024
// ---------------------------------------------------------------------------
__global__ void layernorm_k(const float* __restrict__ x,
                            const float* __restrict__ g,
                            const float* __restrict__ b,
                            float* __restrict__ out) {
    int row = blockIdx.x;
    int t = threadIdx.x;
    const float4* xr = (const float4*)(x + (size_t)row * HID);
    float4 v = xr[t];
    float s  = v.x + v.y + v.z + v.w;
    float ss = v.x*v.x + v.y*v.y + v.z*v.z + v.w*v.w;
    #pragma unroll
    for (int o = 16; o; o >>= 1) {
        s  += __shfl_xor_sync(0xffffffffu, s,  o);
        ss += __shfl_xor_sync(0xffffffffu, ss, o);
    }
    __shared__ float sh[16];
    if ((t & 31) == 0) { sh[t >> 5] = s; sh[8 + (t >> 5)] = ss; }
    __syncthreads();
    s = 0.f; ss = 0.f;
    #pragma unroll
    for (int i = 0; i < 8; i++) { s += sh[i]; ss += sh[8 + i]; }
    float mean = s * (1.0f / HID);
    float var  = ss * (1.0f / HID) - mean * mean;
    float inv  = rsqrtf(var + 1e-5f);
    float4 gv = ((const float4*)g)[t];
    float4 bv = ((const float4*)b)[t];
    float4 o;
    o.x = (v.x - mean) * inv * gv.x + bv.x;
    o.y = (v.y - mean) * inv * gv.y + bv.y;
    o.z = (v.z - mean) * inv * gv.z + bv.z;
    o.w = (v.w - mean) * inv * gv.w + bv.w;
    ((float4*)(out + (size_t)row * HID))[t] = o;
}

// ---------------------------------------------------------------------------
// TF32 MMA GEMM: C = A[M,K] * B[N,K]^T, CTA 128x128, 8 warps of 64x32.
// MODE 1: +bias   MODE 2: +bias, gelu   MODE 3: resid + ls*( . + bias )
// N must be a multiple of 128; M guarded; K multiple of 16.
// ---------------------------------------------------------------------------
template <int MODE>
__global__ void __launch_bounds__(256, 2)
gemm_tf32(const float* __restrict__ A, const float* __restrict__ Bw,
          const float* __restrict__ bias, const float* __restrict__ ls,
          const float* __restrict__ resid, float* __restrict__ C,
          int M, int N, int K) {
    __shared__ float As[2][128][20];
    __shared__ float Bs[2][128][20];

    const int t  = threadIdx.x;
    const int w  = t >> 5;
    const int g  = (t >> 2) & 7;
    const int t4 = t & 3;
    const int wm = (w >> 2) * 64;
    const int wn = (w & 3) * 32;
    const int m0 = blockIdx.y * 128;
    const int n0 = blockIdx.x * 128;

    float d[4][4][4];
    #pragma unroll
    for (int i = 0; i < 4; i++)
        #pragma unroll
        for (int j = 0; j < 4; j++)
            #pragma unroll
            for (int r = 0; r < 4; r++) d[i][j][r] = 0.f;

    const int r_st = t >> 2;          // 0..63
    const int c_st = (t & 3) * 4;     // 0,4,8,12
    const float* Ar0 = A  + (size_t)min(m0 + r_st,      M - 1) * K + c_st;
    const float* Ar1 = A  + (size_t)min(m0 + r_st + 64, M - 1) * K + c_st;
    const float* Br0 = Bw + (size_t)min(n0 + r_st,      N - 1) * K + c_st;
    const float* Br1 = Bw + (size_t)min(n0 + r_st + 64, N - 1) * K + c_st;

    auto stage = [&](int buf, int k0) {
        cp16(&As[buf][r_st     ][c_st], Ar0 + k0, true);
        cp16(&As[buf][r_st + 64][c_st], Ar1 + k0, true);
        cp16(&Bs[buf][r_st     ][c_st], Br0 + k0, true);
        cp16(&Bs[buf][r_st + 64][c_st], Br1 + k0, true);
        cp_commit();
    };

    const int NC = K >> 4;
    stage(0, 0);
    for (int kc = 0; kc < NC; kc++) {
        if (kc + 1 < NC) {
            stage((kc + 1) & 1, (kc + 1) << 4);
            asm volatile("cp.async.wait_group 1;");
        } else {
            asm volatile("cp.async.wait_group 0;");
        }
        __syncthreads();
        const int buf = kc & 1;
        #pragma unroll
        for (int ks = 0; ks < 16; ks += 8) {
            unsigned af[4][4], bf[4][2];
            #pragma unroll
            for (int i = 0; i < 4; i++) {
                int r = wm + i * 16 + g;
                af[i][0] = f2tf(As[buf][r    ][ks + t4]);
                af[i][1] = f2tf(As[buf][r + 8][ks + t4]);
                af[i][2] = f2tf(As[buf][r    ][ks + t4 + 4]);
                af[i][3] = f2tf(As[buf][r + 8][ks + t4 + 4]);
            }
            #pragma unroll
            for (int j = 0; j < 4; j++) {
                int c = wn + j * 8 + g;
                bf[j][0] = f2tf(Bs[buf][c][ks + t4]);
                bf[j][1] = f2tf(Bs[buf][c][ks + t4 + 4]);
            }
            #pragma unroll
            for (int i = 0; i < 4; i++)
                #pragma unroll
                for (int j = 0; j < 4; j++)
                    mma_tf32(d[i][j], af[i], bf[j]);
        }
        __syncthreads();
    }

    // epilogue
    #pragma unroll
    for (int i = 0; i < 4; i++) {
        int rbase = m0 + wm + i * 16 + g;
        #pragma unroll
        for (int rr = 0; rr < 2; rr++) {
            int row = rbase + 8 * rr;
            if (row >= M) continue;
            #pragma unroll
            for (int j = 0; j < 4; j++) {
                int col = n0 + wn + j * 8 + 2 * t4;
                float v0 = d[i][j][rr * 2 + 0];
                float v1 = d[i][j][rr * 2 + 1];
                size_t idx = (size_t)row * N + col;
                if (MODE == 1) {
                    v0 += bias[col]; v1 += bias[col + 1];
                } else if (MODE == 2) {
                    v0 = gelu_f(v0 + bias[col]);
                    v1 = gelu_f(v1 + bias[col + 1]);
                } else if (MODE == 3) {
                    float2 rv = *(const float2*)(resid + idx);
                    v0 = rv.x + ls[col]     * (v0 + bias[col]);
                    v1 = rv.y + ls[col + 1] * (v1 + bias[col + 1]);
                }
                float2 ov = make_float2(v0, v1);
                *(float2*)(C + idx) = ov;
            }
        }
    }
}

// ---------------------------------------------------------------------------
// Scores: per (b,h) S[q,k] = 0.125 * Q·K^T. M=N=1025 (guarded), K=64.
// ---------------------------------------------------------------------------
__global__ void __launch_bounds__(256, 2)
scores_tf32(const float* __restrict__ qkv, float* __restrict__ scores) {
    __shared__ float As[2][128][20];
    __shared__ float Bs[2][128][20];

    const int t  = threadIdx.x;
    const int w  = t >> 5;
    const int g  = (t >> 2) & 7;
    const int t4 = t & 3;
    const int wm = (w >> 2) * 64;
    const int wn = (w & 3) * 32;
    const int z  = blockIdx.z, b = z >> 4, h = z & 15;
    const int m0 = blockIdx.y * 128;
    const int n0 = blockIdx.x * 128;

    const float* Qb = qkv + (size_t)b * SEQ * (3 * HID) + h * HDIM;
    const float* Kb = Qb + HID;

    float d[4][4][4];
    #pragma unroll
    for (int i = 0; i < 4; i++)
        #pragma unroll
        for (int j = 0; j < 4; j++)
            #pragma unroll
            for (int r = 0; r < 4; r++) d[i][j][r] = 0.f;

    const int r_st = t >> 2;
    const int c_st = (t & 3) * 4;
    const float* Ar0 = Qb + (size_t)min(m0 + r_st,      SEQ - 1) * (3 * HID) + c_st;
    const float* Ar1 = Qb + (size_t)min(m0 + r_st + 64, SEQ - 1) * (3 * HID) + c_st;
    const float* Br0 = Kb + (size_t)min(n0 + r_st,      SEQ - 1) * (3 * HID) + c_st;
    const float* Br1 = Kb + (size_t)min(n0 + r_st + 64, SEQ - 1) * (3 * HID) + c_st;

    auto stage = [&](int buf, int k0) {
        cp16(&As[buf][r_st     ][c_st], Ar0 + k0, true);
        cp16(&As[buf][r_st + 64][c_st], Ar1 + k0, true);
        cp16(&Bs[buf][r_st     ][c_st], Br0 + k0, true);
        cp16(&Bs[buf][r_st + 64][c_st], Br1 + k0, true);
        cp_commit();
    };

    const int NC = HDIM >> 4;  // 4
    stage(0, 0);
    for (int kc = 0; kc < NC; kc++) {
        if (kc + 1 < NC) {
            stage((kc + 1) & 1, (kc + 1) << 4);
            asm volatile("cp.async.wait_group 1;");
        } else {
            asm volatile("cp.async.wait_group 0;");
        }
        __syncthreads();
        const int buf = kc & 1;
        #pragma unroll
        for (int ks = 0; ks < 16; ks += 8) {
            unsigned af[4][4], bf[4][2];
            #pragma unroll
            for (int i = 0; i < 4; i++) {
                int r = wm + i * 16 + g;
                af[i][0] = f2tf(As[buf][r    ][ks + t4]);
                af[i][1] = f2tf(As[buf][r + 8][ks + t4]);
                af[i][2] = f2tf(As[buf][r    ][ks + t4 + 4]);
                af[i][3] = f2tf(As[buf][r + 8][ks + t4 + 4]);
            }
            #pragma unroll
            for (int j = 0; j < 4; j++) {
                int c = wn + j * 8 + g;
                bf[j][0] = f2tf(Bs[buf][c][ks + t4]);
                bf[j][1] = f2tf(Bs[buf][c][ks + t4 + 4]);
            }
            #pragma unroll
            for (int i = 0; i < 4; i++)
                #pragma unroll
                for (int j = 0; j < 4; j++)
                    mma_tf32(d[i][j], af[i], bf[j]);
        }
        __syncthreads();
    }

    float* Cb = scores + (size_t)z * SEQ * LDS_SC;
    #pragma unroll
    for (int i = 0; i < 4; i++) {
        int rbase = m0 + wm + i * 16 + g;
        #pragma unroll
        for (int rr = 0; rr < 2; rr++) {
            int row = rbase + 8 * rr;
            if (row >= SEQ) continue;
            #pragma unroll
            for (int j = 0; j < 4; j++) {
                int col = n0 + wn + j * 8 + 2 * t4;
                if (col < SEQ)     Cb[(size_t)row * LDS_SC + col]     = d[i][j][rr*2+0] * 0.125f;
                if (col + 1 < SEQ) Cb[(size_t)row * LDS_SC + col + 1] = d[i][j][rr*2+1] * 0.125f;
            }
        }
    }
}

// ---------------------------------------------------------------------------
// Softmax over rows of length 1025 (ld = 1028; zeroes the 3 pad slots).
// ---------------------------------------------------------------------------
__global__ void softmax_k(float* __restrict__ scores) {
    size_t row = blockIdx.x;
    float* p = scores + row * LDS_SC;
    int t = threadIdx.x;

    float vals[5];
    int cnt = 0;
    float mx = -1e30f;
    for (int i = t; i < SEQ; i += 256) {
        float v = p[i];
        vals[cnt++] = v;
        mx = fmaxf(mx, v);
    }
    __shared__ float sh[8];
    #pragma unroll
    for (int o = 16; o; o >>= 1) mx = fmaxf(mx, __shfl_xor_sync(0xffffffffu, mx, o));
    if ((t & 31) == 0) sh[t >> 5] = mx;
    __syncthreads();
    mx = sh[0];
    #pragma unroll
    for (int i = 1; i < 8; i++) mx = fmaxf(mx, sh[i]);
    __syncthreads();

    float sum = 0.f;
    for (int j = 0; j < cnt; j++) { vals[j] = __expf(vals[j] - mx); sum += vals[j]; }
    #pragma unroll
    for (int o = 16; o; o >>= 1) sum += __shfl_xor_sync(0xffffffffu, sum, o);
    if ((t & 31) == 0) sh[t >> 5] = sum;
    __syncthreads();
    sum = 0.f;
    #pragma unroll
    for (int i = 0; i < 8; i++) sum += sh[i];
    float inv = 1.0f / sum;

    cnt = 0;
    for (int i = t; i < SEQ; i += 256) p[i] = vals[cnt++] * inv;
    if (t < 3) p[SEQ + t] = 0.f;
}

// ---------------------------------------------------------------------------
// PV: per (b,h) O[q,d] = sum_k P[q,k] * V[k,d].  CTA 128x64, 4 warps 64x32.
// K = 1025 (padded chunks with zero-fill), N = 64.
// ---------------------------------------------------------------------------
__global__ void __launch_bounds__(128, 4)
pv_tf32(const float* __restrict__ scores, const float* __restrict__ qkv,
        float* __restrict__ out) {
    __shared__ float As[2][128][20];
    __shared__ float Bs[2][16][72];

    const int t  = threadIdx.x;
    const int w  = t >> 5;          // 0..3
    const int g  = (t >> 2) & 7;
    const int t4 = t & 3;
    const int wm = (w >> 1) * 64;
    const int wn = (w & 1) * 32;
    const int z  = blockIdx.z, b = z >> 4, h = z & 15;
    const int q0 = blockIdx.x * 128;

    const float* Pb = scores + (size_t)z * SEQ * LDS_SC;
    const float* Vb = qkv + (size_t)b * SEQ * (3 * HID) + 2 * HID + h * HDIM;

    float d[4][4][4];
    #pragma unroll
    for (int i = 0; i < 4; i++)
        #pragma unroll
        for (int j = 0; j < 4; j++)
            #pragma unroll
            for (int r = 0; r < 4; r++) d[i][j][r] = 0.f;

    auto stage = [&](int buf, int k0) {
        // A: 128 rows x 16 cols = 512 float4 chunks, 4 per thread
        #pragma unroll
        for (int hh = 0; hh < 4; hh++) {
            int id = t + hh * 128;
            int r  = id >> 2;
            int c4 = (id & 3) * 4;
            int prow = min(q0 + r, SEQ - 1);
            bool ok = (k0 + c4) < LDS_SC;   // cols 1025..1027 are zeroed pads
            cp16(&As[buf][r][c4],
                 Pb + (size_t)prow * LDS_SC + (ok ? (k0 + c4) : 0), ok);
        }
        // B: 16 rows x 64 cols = 256 float4 chunks, 2 per thread
        #pragma unroll
        for (int hh = 0; hh < 2; hh++) {
            int id = t + hh * 128;
            int r  = id >> 4;           // 0..15
            int c4 = (id & 15) * 4;     // 0..60
            int krow = k0 + r;
            bool ok = krow < SEQ;
            cp16(&Bs[buf][r][c4],
                 Vb + (size_t)min(krow, SEQ - 1) * (3 * HID) + c4, ok);
        }
        cp_commit();
    };

    const int NC = (SEQ + 15) >> 4;  // 65
    stage(0, 0);
    for (int kc = 0; kc < NC; kc++) {
        if (kc + 1 < NC) {
            stage((kc + 1) & 1, (kc + 1) << 4);
            asm volatile("cp.async.wait_group 1;");
        } else {
            asm volatile("cp.async.wait_group 0;");
        }
        __syncthreads();
        const int buf = kc & 1;
        #pragma unroll
        for (int ks = 0; ks < 16; ks += 8) {
            unsigned af[4][4], bf[4][2];
            #pragma unroll
            for (int i = 0; i < 4; i++) {
                int r = wm + i * 16 + g;
                af[i][0] = f2tf(As[buf][r    ][ks + t4]);
                af[i][1] = f2tf(As[buf][r + 8][ks + t4]);
                af[i][2] = f2tf(As[buf][r    ][ks + t4 + 4]);
                af[i][3] = f2tf(As[buf][r + 8][ks + t4 + 4]);
            }
            #pragma unroll
            for (int j = 0; j < 4; j++) {
                int c = wn + j * 8 + g;
                bf[j][0] = f2tf(Bs[buf][ks + t4    ][c]);
                bf[j][1] = f2tf(Bs[buf][ks + t4 + 4][c]);
            }
            #pragma unroll
            for (int i = 0; i < 4; i++)
                #pragma unroll
                for (int j = 0; j < 4; j++)
                    mma_tf32(d[i][j], af[i], bf[j]);
        }
        __syncthreads();
    }

    #pragma unroll
    for (int i = 0; i < 4; i++) {
        int rbase = q0 + wm + i * 16 + g;
        #pragma unroll
        for (int rr = 0; rr < 2; rr++) {
            int row = rbase + 8 * rr;
            if (row >= SEQ) continue;
            float* Cr = out + ((size_t)b * SEQ + row) * HID + h * HDIM;
            #pragma unroll
            for (int j = 0; j < 4; j++) {
                int col = wn + j * 8 + 2 * t4;
                float2 ov = make_float2(d[i][j][rr*2+0], d[i][j][rr*2+1]);
                *(float2*)(Cr + col) = ov;
            }
        }
    }
}

// ---------------------------------------------------------------------------
extern "C" void kernel_launch(void* const* d_in, const int* in_sizes, int n_in,
                              void* d_out, int out_size) {
    const float* hidden = (const float*)d_in[0];
    const float* n1g    = (const float*)d_in[1];
    const float* n1b    = (const float*)d_in[2];
    const float* qkvw   = (const float*)d_in[3];
    const float* qkvb   = (const float*)d_in[4];
    const float* projw  = (const float*)d_in[5];
    const float* projb  = (const float*)d_in[6];
    const float* ls1    = (const float*)d_in[7];
    const float* n2g    = (const float*)d_in[8];
    const float* n2b    = (const float*)d_in[9];
    const float* fc1w   = (const float*)d_in[10];
    const float* fc1b   = (const float*)d_in[11];
    const float* fc2w   = (const float*)d_in[12];
    const float* fc2b   = (const float*)d_in[13];
    const float* ls2    = (const float*)d_in[14];
    float* out = (float*)d_out;

    float *xnorm, *qkv, *scores, *attn, *mlp;
    cudaGetSymbolAddress((void**)&xnorm,  g_xnorm);
    cudaGetSymbolAddress((void**)&qkv,    g_qkv);
    cudaGetSymbolAddress((void**)&scores, g_scores);
    cudaGetSymbolAddress((void**)&attn,   g_attn);
    cudaGetSymbolAddress((void**)&mlp,    g_mlp);

    const int MT = (M_TOK + 127) / 128;  // 129
    const int ST = (SEQ + 127) / 128;    // 9

    // 1. LN1
    layernorm_k<<<M_TOK, 256>>>(hidden, n1g, n1b, xnorm);
    // 2. QKV
    gemm_tf32<1><<<dim3(3 * HID / 128, MT), 256>>>(xnorm, qkvw, qkvb, nullptr, nullptr,
                                                   qkv, M_TOK, 3 * HID, HID);
    // 3. scores
    scores_tf32<<<dim3(ST, ST, BATCH * NHEADS), 256>>>(qkv, scores);
    // 4. softmax
    softmax_k<<<BATCH * NHEADS * SEQ, 256>>>(scores);
    // 5. P @ V
    pv_tf32<<<dim3(ST, 1, BATCH * NHEADS), 128>>>(scores, qkv, attn);
    // 6. proj + ls1 residual -> d_out
    gemm_tf32<3><<<dim3(HID / 128, MT), 256>>>(attn, projw, projb, ls1, hidden,
                                               out, M_TOK, HID, HID);
    // 7. LN2
    layernorm_k<<<M_TOK, 256>>>(out, n2g, n2b, xnorm);
    // 8. fc1 + gelu
    gemm_tf32<2><<<dim3(IMED / 128, MT), 256>>>(xnorm, fc1w, fc1b, nullptr, nullptr,
                                                mlp, M_TOK, IMED, HID);
    // 9. fc2 + ls2 residual (in place on d_out)
    gemm_tf32<3><<<dim3(HID / 128, MT), 256>>>(mlp, fc2w, fc2b, ls2, out,
                                               out, M_TOK, HID, IMED);
}

// round 6
// speedup vs baseline: 3.5656x; 1.1760x over previous
#include <cuda_runtime.h>
#include <cuda_bf16.h>
#include <math.h>

// ---------------------------------------------------------------------------
// InternVisionLayer: B=16, S=1025, H=1024, NH=16, HD=64, I=4096, M = 16400
// R5 (= R3 resubmit, static-guard removed): flash-attention fusion
//     (scores+softmax+PV -> one kernel, no 1GB score buffer).
//     Dense GEMMs: TF32 mma m16n8k8, double-buffered cp.async.
// ---------------------------------------------------------------------------

#define M_TOK   16400
#define SEQ     1025
#define BATCH   16
#define HID     1024
#define NHEADS  16
#define HDIM    64
#define IMED    4096

__device__ float g_xnorm [(size_t)M_TOK * HID];
__device__ float g_qkv   [(size_t)M_TOK * 3 * HID];
__device__ float g_attn  [(size_t)M_TOK * HID];
__device__ float g_mlp   [(size_t)M_TOK * IMED];

// ---------------------------------------------------------------------------
// helpers
// ---------------------------------------------------------------------------
__device__ __forceinline__ unsigned f2tf(float x) {
    unsigned u;
    asm("cvt.rna.tf32.f32 %0, %1;" : "=r"(u) : "f"(x));
    return u;
}

__device__ __forceinline__ void mma_tf32(float* d, const unsigned* a, const unsigned* b) {
    asm volatile(
        "mma.sync.aligned.m16n8k8.row.col.f32.tf32.tf32.f32 "
        "{%0,%1,%2,%3}, {%4,%5,%6,%7}, {%8,%9}, {%0,%1,%2,%3};"
        : "+f"(d[0]), "+f"(d[1]), "+f"(d[2]), "+f"(d[3])
        : "r"(a[0]), "r"(a[1]), "r"(a[2]), "r"(a[3]), "r"(b[0]), "r"(b[1]));
}

__device__ __forceinline__ void cp16(void* sdst, const void* gsrc, bool pred) {
    unsigned sa = (unsigned)__cvta_generic_to_shared(sdst);
    int sz = pred ? 16 : 0;
    asm volatile("cp.async.cg.shared.global [%0], [%1], 16, %2;\n"
                 :: "r"(sa), "l"(gsrc), "r"(sz));
}
__device__ __forceinline__ void cp_commit() { asm volatile("cp.async.commit_group;"); }

__device__ __forceinline__ float gelu_f(float v) {
    return 0.5f * v * (1.0f + erff(v * 0.70710678118654752f));
}

// ---------------------------------------------------------------------------
// LayerNorm: one block (256 threads) per row of 1024
// ---------------------------------------------------------------------------
__global__ void layernorm_k(const float* __restrict__ x,
                            const float* __restrict__ g,
                            const float* __restrict__ b,
                            float* __restrict__ out) {
    int row = blockIdx.x;
    int t = threadIdx.x;
    const float4* xr = (const float4*)(x + (size_t)row * HID);
    float4 v = xr[t];
    float s  = v.x + v.y + v.z + v.w;
    float ss = v.x*v.x + v.y*v.y + v.z*v.z + v.w*v.w;
    #pragma unroll
    for (int o = 16; o; o >>= 1) {
        s  += __shfl_xor_sync(0xffffffffu, s,  o);
        ss += __shfl_xor_sync(0xffffffffu, ss, o);
    }
    __shared__ float sh[16];
    if ((t & 31) == 0) { sh[t >> 5] = s; sh[8 + (t >> 5)] = ss; }
    __syncthreads();
    s = 0.f; ss = 0.f;
    #pragma unroll
    for (int i = 0; i < 8; i++) { s += sh[i]; ss += sh[8 + i]; }
    float mean = s * (1.0f / HID);
    float var  = ss * (1.0f / HID) - mean * mean;
    float inv  = rsqrtf(var + 1e-5f);
    float4 gv = ((const float4*)g)[t];
    float4 bv = ((const float4*)b)[t];
    float4 o;
    o.x = (v.x - mean) * inv * gv.x + bv.x;
    o.y = (v.y - mean) * inv * gv.y + bv.y;
    o.z = (v.z - mean) * inv * gv.z + bv.z;
    o.w = (v.w - mean) * inv * gv.w + bv.w;
    ((float4*)(out + (size_t)row * HID))[t] = o;
}

// ---------------------------------------------------------------------------
// TF32 MMA GEMM: C = A[M,K] * B[N,K]^T, CTA 128x128, 8 warps of 64x32.
// MODE 1: +bias   MODE 2: +bias, gelu   MODE 3: resid + ls*( . + bias )
// ---------------------------------------------------------------------------
template <int MODE>
__global__ void __launch_bounds__(256, 2)
gemm_tf32(const float* __restrict__ A, const float* __restrict__ Bw,
          const float* __restrict__ bias, const float* __restrict__ ls,
          const float* __restrict__ resid, float* __restrict__ C,
          int M, int N, int K) {
    __shared__ float As[2][128][20];
    __shared__ float Bs[2][128][20];

    const int t  = threadIdx.x;
    const int w  = t >> 5;
    const int g  = (t >> 2) & 7;
    const int t4 = t & 3;
    const int wm = (w >> 2) * 64;
    const int wn = (w & 3) * 32;
    const int m0 = blockIdx.y * 128;
    const int n0 = blockIdx.x * 128;

    float d[4][4][4];
    #pragma unroll
    for (int i = 0; i < 4; i++)
        #pragma unroll
        for (int j = 0; j < 4; j++)
            #pragma unroll
            for (int r = 0; r < 4; r++) d[i][j][r] = 0.f;

    const int r_st = t >> 2;
    const int c_st = (t & 3) * 4;
    const float* Ar0 = A  + (size_t)min(m0 + r_st,      M - 1) * K + c_st;
    const float* Ar1 = A  + (size_t)min(m0 + r_st + 64, M - 1) * K + c_st;
    const float* Br0 = Bw + (size_t)min(n0 + r_st,      N - 1) * K + c_st;
    const float* Br1 = Bw + (size_t)min(n0 + r_st + 64, N - 1) * K + c_st;

    auto stage = [&](int buf, int k0) {
        cp16(&As[buf][r_st     ][c_st], Ar0 + k0, true);
        cp16(&As[buf][r_st + 64][c_st], Ar1 + k0, true);
        cp16(&Bs[buf][r_st     ][c_st], Br0 + k0, true);
        cp16(&Bs[buf][r_st + 64][c_st], Br1 + k0, true);
        cp_commit();
    };

    const int NC = K >> 4;
    stage(0, 0);
    for (int kc = 0; kc < NC; kc++) {
        if (kc + 1 < NC) {
            stage((kc + 1) & 1, (kc + 1) << 4);
            asm volatile("cp.async.wait_group 1;");
        } else {
            asm volatile("cp.async.wait_group 0;");
        }
        __syncthreads();
        const int buf = kc & 1;
        #pragma unroll
        for (int ks = 0; ks < 16; ks += 8) {
            unsigned af[4][4], bf[4][2];
            #pragma unroll
            for (int i = 0; i < 4; i++) {
                int r = wm + i * 16 + g;
                af[i][0] = f2tf(As[buf][r    ][ks + t4]);
                af[i][1] = f2tf(As[buf][r + 8][ks + t4]);
                af[i][2] = f2tf(As[buf][r    ][ks + t4 + 4]);
                af[i][3] = f2tf(As[buf][r + 8][ks + t4 + 4]);
            }
            #pragma unroll
            for (int j = 0; j < 4; j++) {
                int c = wn + j * 8 + g;
                bf[j][0] = f2tf(Bs[buf][c][ks + t4]);
                bf[j][1] = f2tf(Bs[buf][c][ks + t4 + 4]);
            }
            #pragma unroll
            for (int i = 0; i < 4; i++)
                #pragma unroll
                for (int j = 0; j < 4; j++)
                    mma_tf32(d[i][j], af[i], bf[j]);
        }
        __syncthreads();
    }

    #pragma unroll
    for (int i = 0; i < 4; i++) {
        int rbase = m0 + wm + i * 16 + g;
        #pragma unroll
        for (int rr = 0; rr < 2; rr++) {
            int row = rbase + 8 * rr;
            if (row >= M) continue;
            #pragma unroll
            for (int j = 0; j < 4; j++) {
                int col = n0 + wn + j * 8 + 2 * t4;
                float v0 = d[i][j][rr * 2 + 0];
                float v1 = d[i][j][rr * 2 + 1];
                size_t idx = (size_t)row * N + col;
                if (MODE == 1) {
                    v0 += bias[col]; v1 += bias[col + 1];
                } else if (MODE == 2) {
                    v0 = gelu_f(v0 + bias[col]);
                    v1 = gelu_f(v1 + bias[col + 1]);
                } else if (MODE == 3) {
                    float2 rv = *(const float2*)(resid + idx);
                    v0 = rv.x + ls[col]     * (v0 + bias[col]);
                    v1 = rv.y + ls[col + 1] * (v1 + bias[col + 1]);
                }
                float2 ov = make_float2(v0, v1);
                *(float2*)(C + idx) = ov;
            }
        }
    }
}

// ---------------------------------------------------------------------------
// Flash attention: per CTA = (q-tile 128, b*h). 8 warps, each owns 16 q rows.
// KV tiles of 64, double-buffered cp.async; K/V pre-converted to tf32 bits
// in smem; P roundtrips via warp-private smem (no block sync needed).
// SMEM: Ks[2][64][68] | Vs[2][64][72] | Ps[128][68]   (~104 KB, dynamic)
// ---------------------------------------------------------------------------
#define KT       64
#define KSS      68
#define VSS      72
#define NIT      17        // ceil(1025/64)
#define SM_KS    0
#define SM_VS    (2 * 64 * KSS)                 // 8704
#define SM_PS    (SM_VS + 2 * 64 * VSS)         // 17920
#define SM_TOT   ((SM_PS + 128 * KSS) * 4)      // 106496 bytes

__global__ void __launch_bounds__(256, 1)
flash_attn(const float* __restrict__ qkv, float* __restrict__ out) {
    extern __shared__ float sm[];
    float* Ksm = sm + SM_KS;
    float* Vsm = sm + SM_VS;
    float* Psm = sm + SM_PS;
    unsigned* Psu = (unsigned*)Psm;

    const int t  = threadIdx.x;
    const int w  = t >> 5;
    const int lane = t & 31;
    const int g  = lane >> 2;
    const int t4 = lane & 3;
    const int q0 = blockIdx.x * 128;
    const int z  = blockIdx.y, b = z >> 4, h = z & 15;

    const float* Qg = qkv + (size_t)b * SEQ * (3 * HID) + h * HDIM;
    const float* Kg = Qg + HID;
    const float* Vg = Qg + 2 * HID;

    // ---- stage Q (into Psm scratch) + KV tile 0 ----
    #pragma unroll
    for (int i = 0; i < 8; i++) {
        int id = t + i * 256;
        int r = id >> 4, c4 = (id & 15) * 4;
        int row = min(q0 + r, SEQ - 1);
        cp16(&Psm[r * KSS + c4], Qg + (size_t)row * (3 * HID) + c4, true);
    }
    #pragma unroll
    for (int i = 0; i < 4; i++) {
        int id = t + i * 256;
        int r = id >> 4, c4 = (id & 15) * 4;
        int row = min(r, SEQ - 1);
        cp16(&Ksm[r * KSS + c4], Kg + (size_t)row * (3 * HID) + c4, true);
        cp16(&Vsm[r * VSS + c4], Vg + (size_t)row * (3 * HID) + c4, true);
    }
    cp_commit();
    asm volatile("cp.async.wait_group 0;");
    __syncthreads();

    // convert KV buf0 in place to tf32 bits
    #pragma unroll
    for (int i = 0; i < 16; i++) {
        int id = t + i * 256;
        int r = id >> 6, c = id & 63;
        float* pk = &Ksm[r * KSS + c];
        *(unsigned*)pk = f2tf(*pk);
        float* pv = &Vsm[r * VSS + c];
        *(unsigned*)pv = f2tf(*pv);
    }

    // Q fragments in registers, pre-scaled by HD^-0.5, tf32 bits
    unsigned qf[8][4];
    {
        const int r0 = w * 16 + g;
        #pragma unroll
        for (int kc = 0; kc < 8; kc++) {
            qf[kc][0] = f2tf(Psm[(r0    ) * KSS + kc * 8 + t4    ] * 0.125f);
            qf[kc][1] = f2tf(Psm[(r0 + 8) * KSS + kc * 8 + t4    ] * 0.125f);
            qf[kc][2] = f2tf(Psm[(r0    ) * KSS + kc * 8 + t4 + 4] * 0.125f);
            qf[kc][3] = f2tf(Psm[(r0 + 8) * KSS + kc * 8 + t4 + 4] * 0.125f);
        }
    }
    __syncthreads();   // Q frags read; KV converts visible; Psm free for P

    float m0 = -1e30f, m1 = -1e30f, l0 = 0.f, l1 = 0.f;
    float o[8][4];
    #pragma unroll
    for (int j = 0; j < 8; j++)
        #pragma unroll
        for (int r = 0; r < 4; r++) o[j][r] = 0.f;

    for (int it = 0; it < NIT; it++) {
        const int buf = it & 1;
        const int kv0 = it * KT;

        // prefetch next KV tile
        if (it + 1 < NIT) {
            int nkv = kv0 + KT;
            int nb = buf ^ 1;
            #pragma unroll
            for (int i = 0; i < 4; i++) {
                int id = t + i * 256;
                int r = id >> 4, c4 = (id & 15) * 4;
                int row = min(nkv + r, SEQ - 1);
                cp16(&Ksm[(nb * 64 + r) * KSS + c4], Kg + (size_t)row * (3 * HID) + c4, true);
                cp16(&Vsm[(nb * 64 + r) * VSS + c4], Vg + (size_t)row * (3 * HID) + c4, true);
            }
            cp_commit();
        }

        // ---- S = Q K^T  (warp tile 16 x 64) ----
        const float* Kb = Ksm + buf * 64 * KSS;
        float s[8][4];
        #pragma unroll
        for (int j = 0; j < 8; j++)
            #pragma unroll
            for (int r = 0; r < 4; r++) s[j][r] = 0.f;
        #pragma unroll
        for (int kc = 0; kc < 8; kc++) {
            #pragma unroll
            for (int j = 0; j < 8; j++) {
                unsigned bf[2];
                bf[0] = *(const unsigned*)&Kb[(j * 8 + g) * KSS + kc * 8 + t4    ];
                bf[1] = *(const unsigned*)&Kb[(j * 8 + g) * KSS + kc * 8 + t4 + 4];
                mma_tf32(s[j], qf[kc], bf);
            }
        }

        // ---- mask tail columns ----
        const int lim = SEQ - kv0;
        if (lim < KT) {
            #pragma unroll
            for (int j = 0; j < 8; j++) {
                int c = j * 8 + 2 * t4;
                if (c     >= lim) { s[j][0] = -1e30f; s[j][2] = -1e30f; }
                if (c + 1 >= lim) { s[j][1] = -1e30f; s[j][3] = -1e30f; }
            }
        }

        // ---- online softmax (rows g and g+8, warp-local) ----
        float mx0 = -1e30f, mx1 = -1e30f;
        #pragma unroll
        for (int j = 0; j < 8; j++) {
            mx0 = fmaxf(mx0, fmaxf(s[j][0], s[j][1]));
            mx1 = fmaxf(mx1, fmaxf(s[j][2], s[j][3]));
        }
        mx0 = fmaxf(mx0, __shfl_xor_sync(0xffffffffu, mx0, 1));
        mx0 = fmaxf(mx0, __shfl_xor_sync(0xffffffffu, mx0, 2));
        mx1 = fmaxf(mx1, __shfl_xor_sync(0xffffffffu, mx1, 1));
        mx1 = fmaxf(mx1, __shfl_xor_sync(0xffffffffu, mx1, 2));

        float mn0 = fmaxf(m0, mx0), mn1 = fmaxf(m1, mx1);
        float a0 = __expf(m0 - mn0), a1 = __expf(m1 - mn1);
        m0 = mn0; m1 = mn1;

        float rs0 = 0.f, rs1 = 0.f;
        #pragma unroll
        for (int j = 0; j < 8; j++) {
            s[j][0] = __expf(s[j][0] - m0);
            s[j][1] = __expf(s[j][1] - m0);
            s[j][2] = __expf(s[j][2] - m1);
            s[j][3] = __expf(s[j][3] - m1);
            rs0 += s[j][0] + s[j][1];
            rs1 += s[j][2] + s[j][3];
        }
        rs0 += __shfl_xor_sync(0xffffffffu, rs0, 1);
        rs0 += __shfl_xor_sync(0xffffffffu, rs0, 2);
        rs1 += __shfl_xor_sync(0xffffffffu, rs1, 1);
        rs1 += __shfl_xor_sync(0xffffffffu, rs1, 2);
        l0 = l0 * a0 + rs0;
        l1 = l1 * a1 + rs1;

        // rescale O, write P (tf32 bits) to warp-private smem
        const int r0 = w * 16 + g;
        #pragma unroll
        for (int j = 0; j < 8; j++) {
            o[j][0] *= a0; o[j][1] *= a0; o[j][2] *= a1; o[j][3] *= a1;
            uint2 p01 = make_uint2(f2tf(s[j][0]), f2tf(s[j][1]));
            uint2 p23 = make_uint2(f2tf(s[j][2]), f2tf(s[j][3]));
            *(uint2*)&Psu[(r0    ) * KSS + j * 8 + 2 * t4] = p01;
            *(uint2*)&Psu[(r0 + 8) * KSS + j * 8 + 2 * t4] = p23;
        }
        __syncwarp();

        // ---- O += P V  (k dim = 64 kv) ----
        const float* Vb = Vsm + buf * 64 * VSS;
        #pragma unroll
        for (int kc = 0; kc < 8; kc++) {
            unsigned au[4];
            au[0] = Psu[(r0    ) * KSS + kc * 8 + t4    ];
            au[1] = Psu[(r0 + 8) * KSS + kc * 8 + t4    ];
            au[2] = Psu[(r0    ) * KSS + kc * 8 + t4 + 4];
            au[3] = Psu[(r0 + 8) * KSS + kc * 8 + t4 + 4];
            #pragma unroll
            for (int j = 0; j < 8; j++) {
                unsigned bf[2];
                bf[0] = *(const unsigned*)&Vb[(kc * 8 + t4    ) * VSS + j * 8 + g];
                bf[1] = *(const unsigned*)&Vb[(kc * 8 + t4 + 4) * VSS + j * 8 + g];
                mma_tf32(o[j], au, bf);
            }
        }

        // finish prefetch + convert next buf
        if (it + 1 < NIT) {
            asm volatile("cp.async.wait_group 0;");
            __syncthreads();
            int nb = buf ^ 1;
            #pragma unroll
            for (int i = 0; i < 16; i++) {
                int id = t + i * 256;
                int r = id >> 6, c = id & 63;
                float* pk = &Ksm[(nb * 64 + r) * KSS + c];
                *(unsigned*)pk = f2tf(*pk);
                float* pv = &Vsm[(nb * 64 + r) * VSS + c];
                *(unsigned*)pv = f2tf(*pv);
            }
            __syncthreads();
        }
    }

    // ---- epilogue: normalize and store ----
    float inv0 = 1.f / l0, inv1 = 1.f / l1;
    int row0 = q0 + w * 16 + g;
    int row1 = row0 + 8;
    #pragma unroll
    for (int j = 0; j < 8; j++) {
        int col = j * 8 + 2 * t4;
        if (row0 < SEQ) {
            float2 ov = make_float2(o[j][0] * inv0, o[j][1] * inv0);
            *(float2*)(out + ((size_t)b * SEQ + row0) * HID + h * HDIM + col) = ov;
        }
        if (row1 < SEQ) {
            float2 ov = make_float2(o[j][2] * inv1, o[j][3] * inv1);
            *(float2*)(out + ((size_t)b * SEQ + row1) * HID + h * HDIM + col) = ov;
        }
    }
}

// ---------------------------------------------------------------------------
extern "C" void kernel_launch(void* const* d_in, const int* in_sizes, int n_in,
                              void* d_out, int out_size) {
    const float* hidden = (const float*)d_in[0];
    const float* n1g    = (const float*)d_in[1];
    const float* n1b    = (const float*)d_in[2];
    const float* qkvw   = (const float*)d_in[3];
    const float* qkvb   = (const float*)d_in[4];
    const float* projw  = (const float*)d_in[5];
    const float* projb  = (const float*)d_in[6];
    const float* ls1    = (const float*)d_in[7];
    const float* n2g    = (const float*)d_in[8];
    const float* n2b    = (const float*)d_in[9];
    const float* fc1w   = (const float*)d_in[10];
    const float* fc1b   = (const float*)d_in[11];
    const float* fc2w   = (const float*)d_in[12];
    const float* fc2b   = (const float*)d_in[13];
    const float* ls2    = (const float*)d_in[14];
    float* out = (float*)d_out;

    float *xnorm, *qkv, *attn, *mlp;
    cudaGetSymbolAddress((void**)&xnorm, g_xnorm);
    cudaGetSymbolAddress((void**)&qkv,   g_qkv);
    cudaGetSymbolAddress((void**)&attn,  g_attn);
    cudaGetSymbolAddress((void**)&mlp,   g_mlp);

    // Idempotent host-side attribute set (no static guard; capture-safe).
    cudaFuncSetAttribute(flash_attn, cudaFuncAttributeMaxDynamicSharedMemorySize,
                         SM_TOT);

    const int MT = (M_TOK + 127) / 128;  // 129
    const int QT = (SEQ + 127) / 128;    // 9

    // 1. LN1
    layernorm_k<<<M_TOK, 256>>>(hidden, n1g, n1b, xnorm);
    // 2. QKV
    gemm_tf32<1><<<dim3(3 * HID / 128, MT), 256>>>(xnorm, qkvw, qkvb, nullptr, nullptr,
                                                   qkv, M_TOK, 3 * HID, HID);
    // 3-5. fused attention
    flash_attn<<<dim3(QT, BATCH * NHEADS), 256, SM_TOT>>>(qkv, attn);
    // 6. proj + ls1 residual -> d_out
    gemm_tf32<3><<<dim3(HID / 128, MT), 256>>>(attn, projw, projb, ls1, hidden,
                                               out, M_TOK, HID, HID);
    // 7. LN2
    layernorm_k<<<M_TOK, 256>>>(out, n2g, n2b, xnorm);
    // 8. fc1 + gelu
    gemm_tf32<2><<<dim3(IMED / 128, MT), 256>>>(xnorm, fc1w, fc1b, nullptr, nullptr,
                                                mlp, M_TOK, IMED, HID);
    // 9. fc2 + ls2 residual (in place on d_out)
    gemm_tf32<3><<<dim3(HID / 128, MT), 256>>>(mlp, fc2w, fc2b, ls2, out,
                                               out, M_TOK, HID, IMED);
}

// round 7
// speedup vs baseline: 6.4631x; 1.8126x over previous
#include <cuda_runtime.h>
#include <cuda_bf16.h>
#include <math.h>

// ---------------------------------------------------------------------------
// InternVisionLayer: B=16, S=1025, H=1024, NH=16, HD=64, I=4096, M = 16400
// R6: dense GEMMs -> bf16 m16n8k16 MMA + ldmatrix (weights pre-converted to
//     bf16 scratch; LN / flash emit bf16 activations directly).
//     Flash attention stays TF32 on fp32 QKV (unchanged structure).
// ---------------------------------------------------------------------------

#define M_TOK   16400
#define SEQ     1025
#define BATCH   16
#define HID     1024
#define NHEADS  16
#define HDIM    64
#define IMED    4096

__device__ __nv_bfloat16 g_xnorm [(size_t)M_TOK * HID];
__device__ float         g_qkv   [(size_t)M_TOK * 3 * HID];
__device__ __nv_bfloat16 g_attn  [(size_t)M_TOK * HID];
__device__ __nv_bfloat16 g_mlp   [(size_t)M_TOK * IMED];
__device__ __nv_bfloat16 g_qkvw  [(size_t)3 * HID * HID];
__device__ __nv_bfloat16 g_projw [(size_t)HID * HID];
__device__ __nv_bfloat16 g_fc1w  [(size_t)IMED * HID];
__device__ __nv_bfloat16 g_fc2w  [(size_t)HID * IMED];

// ---------------------------------------------------------------------------
// helpers
// ---------------------------------------------------------------------------
__device__ __forceinline__ unsigned f2tf(float x) {
    unsigned u;
    asm("cvt.rna.tf32.f32 %0, %1;" : "=r"(u) : "f"(x));
    return u;
}

__device__ __forceinline__ void mma_tf32(float* d, const unsigned* a, const unsigned* b) {
    asm volatile(
        "mma.sync.aligned.m16n8k8.row.col.f32.tf32.tf32.f32 "
        "{%0,%1,%2,%3}, {%4,%5,%6,%7}, {%8,%9}, {%0,%1,%2,%3};"
        : "+f"(d[0]), "+f"(d[1]), "+f"(d[2]), "+f"(d[3])
        : "r"(a[0]), "r"(a[1]), "r"(a[2]), "r"(a[3]), "r"(b[0]), "r"(b[1]));
}

__device__ __forceinline__ void mma_bf16(float* d, const unsigned* a, const unsigned* b) {
    asm volatile(
        "mma.sync.aligned.m16n8k16.row.col.f32.bf16.bf16.f32 "
        "{%0,%1,%2,%3}, {%4,%5,%6,%7}, {%8,%9}, {%0,%1,%2,%3};"
        : "+f"(d[0]), "+f"(d[1]), "+f"(d[2]), "+f"(d[3])
        : "r"(a[0]), "r"(a[1]), "r"(a[2]), "r"(a[3]), "r"(b[0]), "r"(b[1]));
}

__device__ __forceinline__ void ldm_x4(unsigned& r0, unsigned& r1, unsigned& r2,
                                       unsigned& r3, unsigned saddr) {
    asm volatile("ldmatrix.sync.aligned.m8n8.x4.shared.b16 {%0,%1,%2,%3}, [%4];"
                 : "=r"(r0), "=r"(r1), "=r"(r2), "=r"(r3) : "r"(saddr));
}

__device__ __forceinline__ void cp16(void* sdst, const void* gsrc, bool pred) {
    unsigned sa = (unsigned)__cvta_generic_to_shared(sdst);
    int sz = pred ? 16 : 0;
    asm volatile("cp.async.cg.shared.global [%0], [%1], 16, %2;\n"
                 :: "r"(sa), "l"(gsrc), "r"(sz));
}
__device__ __forceinline__ void cp16s(unsigned sa, const void* gsrc) {
    asm volatile("cp.async.cg.shared.global [%0], [%1], 16;\n"
                 :: "r"(sa), "l"(gsrc));
}
__device__ __forceinline__ void cp_commit() { asm volatile("cp.async.commit_group;"); }

__device__ __forceinline__ float gelu_f(float v) {
    return 0.5f * v * (1.0f + erff(v * 0.70710678118654752f));
}

// byte offset inside a 128-row x 64-byte tile, XOR-swizzled (ldmatrix
// conflict-free: 8 consecutive rows at fixed c hit 8 distinct 16B slots)
__device__ __forceinline__ unsigned swz(int r, int c) {
    return (unsigned)(r * 64 + (((c ^ (r >> 1)) & 3) << 4));
}

// ---------------------------------------------------------------------------
// fp32 -> bf16 converter (weights)
// ---------------------------------------------------------------------------
__global__ void f2bf_k(const float* __restrict__ in, __nv_bfloat16* __restrict__ out,
                       int n4) {
    int i = blockIdx.x * blockDim.x + threadIdx.x;
    if (i < n4) {
        float4 v = ((const float4*)in)[i];
        ((__nv_bfloat162*)out)[2 * i + 0] = __floats2bfloat162_rn(v.x, v.y);
        ((__nv_bfloat162*)out)[2 * i + 1] = __floats2bfloat162_rn(v.z, v.w);
    }
}

// ---------------------------------------------------------------------------
// LayerNorm: one block (256 threads) per row of 1024; bf16 output
// ---------------------------------------------------------------------------
__global__ void layernorm_k(const float* __restrict__ x,
                            const float* __restrict__ g,
                            const float* __restrict__ b,
                            __nv_bfloat16* __restrict__ out) {
    int row = blockIdx.x;
    int t = threadIdx.x;
    const float4* xr = (const float4*)(x + (size_t)row * HID);
    float4 v = xr[t];
    float s  = v.x + v.y + v.z + v.w;
    float ss = v.x*v.x + v.y*v.y + v.z*v.z + v.w*v.w;
    #pragma unroll
    for (int o = 16; o; o >>= 1) {
        s  += __shfl_xor_sync(0xffffffffu, s,  o);
        ss += __shfl_xor_sync(0xffffffffu, ss, o);
    }
    __shared__ float sh[16];
    if ((t & 31) == 0) { sh[t >> 5] = s; sh[8 + (t >> 5)] = ss; }
    __syncthreads();
    s = 0.f; ss = 0.f;
    #pragma unroll
    for (int i = 0; i < 8; i++) { s += sh[i]; ss += sh[8 + i]; }
    float mean = s * (1.0f / HID);
    float var  = ss * (1.0f / HID) - mean * mean;
    float inv  = rsqrtf(var + 1e-5f);
    float4 gv = ((const float4*)g)[t];
    float4 bv = ((const float4*)b)[t];
    __nv_bfloat162* orow = (__nv_bfloat162*)(out + (size_t)row * HID);
    orow[2 * t + 0] = __floats2bfloat162_rn((v.x - mean) * inv * gv.x + bv.x,
                                            (v.y - mean) * inv * gv.y + bv.y);
    orow[2 * t + 1] = __floats2bfloat162_rn((v.z - mean) * inv * gv.z + bv.z,
                                            (v.w - mean) * inv * gv.w + bv.w);
}

// ---------------------------------------------------------------------------
// bf16 MMA GEMM: C = A[M,K] * B[N,K]^T, CTA 128x128, 8 warps of 64x32.
// m16n8k16 + ldmatrix.x4, XOR-swizzled smem, K-chunk 32, double buffered.
// MODE 1: +bias -> fp32   MODE 2: +bias, gelu -> bf16
// MODE 3: resid + ls*( . + bias ) -> fp32
// ---------------------------------------------------------------------------
template <int MODE>
__global__ void __launch_bounds__(256, 2)
gemm_bf16(const __nv_bfloat16* __restrict__ A, const __nv_bfloat16* __restrict__ Bw,
          const float* __restrict__ bias, const float* __restrict__ ls,
          const float* __restrict__ resid, float* __restrict__ Cf,
          __nv_bfloat16* __restrict__ Cb, int M, int N, int K) {
    __shared__ __align__(128) char sm[2][2][128 * 64];

    const int t  = threadIdx.x;
    const int w  = t >> 5;
    const int lane = t & 31;
    const int g  = lane >> 2;
    const int t4 = lane & 3;
    const int wm = (w >> 2) * 64;
    const int wn = (w & 3) * 32;
    const int m0 = blockIdx.y * 128;
    const int n0 = blockIdx.x * 128;

    const unsigned smb = (unsigned)__cvta_generic_to_shared(&sm[0][0][0]);

    float d[4][4][4];
    #pragma unroll
    for (int i = 0; i < 4; i++)
        #pragma unroll
        for (int j = 0; j < 4; j++)
            #pragma unroll
            for (int r = 0; r < 4; r++) d[i][j][r] = 0.f;

    // staging: each thread owns rows r0, r0+64 at 16B chunk c (of 4)
    const int r0 = t >> 2;
    const int c  = t & 3;
    const __nv_bfloat16* gA0 = A  + (size_t)min(m0 + r0,      M - 1) * K + c * 8;
    const __nv_bfloat16* gA1 = A  + (size_t)min(m0 + r0 + 64, M - 1) * K + c * 8;
    const __nv_bfloat16* gB0 = Bw + (size_t)(n0 + r0)      * K + c * 8;
    const __nv_bfloat16* gB1 = Bw + (size_t)(n0 + r0 + 64) * K + c * 8;

    auto stage = [&](int buf, int k0) {
        unsigned ab = smb + buf * 16384;
        cp16s(ab         + swz(r0,      c), gA0 + k0);
        cp16s(ab         + swz(r0 + 64, c), gA1 + k0);
        cp16s(ab + 8192  + swz(r0,      c), gB0 + k0);
        cp16s(ab + 8192  + swz(r0 + 64, c), gB1 + k0);
        cp_commit();
    };

    // ldmatrix address components (lane-dependent)
    const int a_row = (lane & 15);           // + wm + i*16
    const int a_c   = (lane >> 4);           // + 2s
    const int b_row = ((lane >> 4) << 3) + (lane & 7);  // + wn + jj*16
    const int b_c   = ((lane >> 3) & 1);     // + 2s

    const int NC = K >> 5;
    stage(0, 0);
    for (int kc = 0; kc < NC; kc++) {
        if (kc + 1 < NC) {
            stage((kc + 1) & 1, (kc + 1) << 5);
            asm volatile("cp.async.wait_group 1;");
        } else {
            asm volatile("cp.async.wait_group 0;");
        }
        __syncthreads();
        const unsigned ab = smb + (kc & 1) * 16384;
        const unsigned bb = ab + 8192;
        #pragma unroll
        for (int s = 0; s < 2; s++) {
            unsigned af[4][4], bf[2][4];
            #pragma unroll
            for (int i = 0; i < 4; i++)
                ldm_x4(af[i][0], af[i][1], af[i][2], af[i][3],
                       ab + swz(wm + i * 16 + a_row, 2 * s + a_c));
            #pragma unroll
            for (int jj = 0; jj < 2; jj++)
                ldm_x4(bf[jj][0], bf[jj][1], bf[jj][2], bf[jj][3],
                       bb + swz(wn + jj * 16 + b_row, 2 * s + b_c));
            #pragma unroll
            for (int i = 0; i < 4; i++)
                #pragma unroll
                for (int j = 0; j < 4; j++)
                    mma_bf16(d[i][j], af[i], &bf[j >> 1][(j & 1) * 2]);
        }
        __syncthreads();
    }

    // epilogue
    #pragma unroll
    for (int i = 0; i < 4; i++) {
        int rbase = m0 + wm + i * 16 + g;
        #pragma unroll
        for (int rr = 0; rr < 2; rr++) {
            int row = rbase + 8 * rr;
            if (row >= M) continue;
            #pragma unroll
            for (int j = 0; j < 4; j++) {
                int col = n0 + wn + j * 8 + 2 * t4;
                float v0 = d[i][j][rr * 2 + 0];
                float v1 = d[i][j][rr * 2 + 1];
                size_t idx = (size_t)row * N + col;
                if (MODE == 1) {
                    v0 += bias[col]; v1 += bias[col + 1];
                    *(float2*)(Cf + idx) = make_float2(v0, v1);
                } else if (MODE == 2) {
                    v0 = gelu_f(v0 + bias[col]);
                    v1 = gelu_f(v1 + bias[col + 1]);
                    *(__nv_bfloat162*)(Cb + idx) = __floats2bfloat162_rn(v0, v1);
                } else {
                    float2 rv = *(const float2*)(resid + idx);
                    v0 = rv.x + ls[col]     * (v0 + bias[col]);
                    v1 = rv.y + ls[col + 1] * (v1 + bias[col + 1]);
                    *(float2*)(Cf + idx) = make_float2(v0, v1);
                }
            }
        }
    }
}

// ---------------------------------------------------------------------------
// Flash attention (TF32, fp32 QKV in, bf16 out). Per CTA = (q-tile 128, b*h).
// 8 warps, each owns 16 q rows. KV tiles of 64, double-buffered cp.async.
// SMEM: Ks[2][64][68] | Vs[2][64][72] | Ps[128][68]   (~104 KB, dynamic)
// ---------------------------------------------------------------------------
#define KT       64
#define KSS      68
#define VSS      72
#define NIT      17        // ceil(1025/64)
#define SM_KS    0
#define SM_VS    (2 * 64 * KSS)                 // 8704
#define SM_PS    (SM_VS + 2 * 64 * VSS)         // 17920
#define SM_TOT   ((SM_PS + 128 * KSS) * 4)      // 106496 bytes

__global__ void __launch_bounds__(256, 1)
flash_attn(const float* __restrict__ qkv, __nv_bfloat16* __restrict__ out) {
    extern __shared__ float smf[];
    float* Ksm = smf + SM_KS;
    float* Vsm = smf + SM_VS;
    float* Psm = smf + SM_PS;
    unsigned* Psu = (unsigned*)Psm;

    const int t  = threadIdx.x;
    const int w  = t >> 5;
    const int lane = t & 31;
    const int g  = lane >> 2;
    const int t4 = lane & 3;
    const int q0 = blockIdx.x * 128;
    const int z  = blockIdx.y, b = z >> 4, h = z & 15;

    const float* Qg = qkv + (size_t)b * SEQ * (3 * HID) + h * HDIM;
    const float* Kg = Qg + HID;
    const float* Vg = Qg + 2 * HID;

    // ---- stage Q (into Psm scratch) + KV tile 0 ----
    #pragma unroll
    for (int i = 0; i < 8; i++) {
        int id = t + i * 256;
        int r = id >> 4, c4 = (id & 15) * 4;
        int row = min(q0 + r, SEQ - 1);
        cp16(&Psm[r * KSS + c4], Qg + (size_t)row * (3 * HID) + c4, true);
    }
    #pragma unroll
    for (int i = 0; i < 4; i++) {
        int id = t + i * 256;
        int r = id >> 4, c4 = (id & 15) * 4;
        int row = min(r, SEQ - 1);
        cp16(&Ksm[r * KSS + c4], Kg + (size_t)row * (3 * HID) + c4, true);
        cp16(&Vsm[r * VSS + c4], Vg + (size_t)row * (3 * HID) + c4, true);
    }
    cp_commit();
    asm volatile("cp.async.wait_group 0;");
    __syncthreads();

    // convert KV buf0 in place to tf32 bits
    #pragma unroll
    for (int i = 0; i < 16; i++) {
        int id = t + i * 256;
        int r = id >> 6, c = id & 63;
        float* pk = &Ksm[r * KSS + c];
        *(unsigned*)pk = f2tf(*pk);
        float* pv = &Vsm[r * VSS + c];
        *(unsigned*)pv = f2tf(*pv);
    }

    // Q fragments in registers, pre-scaled by HD^-0.5, tf32 bits
    unsigned qf[8][4];
    {
        const int r0 = w * 16 + g;
        #pragma unroll
        for (int kc = 0; kc < 8; kc++) {
            qf[kc][0] = f2tf(Psm[(r0    ) * KSS + kc * 8 + t4    ] * 0.125f);
            qf[kc][1] = f2tf(Psm[(r0 + 8) * KSS + kc * 8 + t4    ] * 0.125f);
            qf[kc][2] = f2tf(Psm[(r0    ) * KSS + kc * 8 + t4 + 4] * 0.125f);
            qf[kc][3] = f2tf(Psm[(r0 + 8) * KSS + kc * 8 + t4 + 4] * 0.125f);
        }
    }
    __syncthreads();   // Q frags read; KV converts visible; Psm free for P

    float m0 = -1e30f, m1 = -1e30f, l0 = 0.f, l1 = 0.f;
    float o[8][4];
    #pragma unroll
    for (int j = 0; j < 8; j++)
        #pragma unroll
        for (int r = 0; r < 4; r++) o[j][r] = 0.f;

    for (int it = 0; it < NIT; it++) {
        const int buf = it & 1;
        const int kv0 = it * KT;

        if (it + 1 < NIT) {
            int nkv = kv0 + KT;
            int nb = buf ^ 1;
            #pragma unroll
            for (int i = 0; i < 4; i++) {
                int id = t + i * 256;
                int r = id >> 4, c4 = (id & 15) * 4;
                int row = min(nkv + r, SEQ - 1);
                cp16(&Ksm[(nb * 64 + r) * KSS + c4], Kg + (size_t)row * (3 * HID) + c4, true);
                cp16(&Vsm[(nb * 64 + r) * VSS + c4], Vg + (size_t)row * (3 * HID) + c4, true);
            }
            cp_commit();
        }

        // ---- S = Q K^T ----
        const float* Kb = Ksm + buf * 64 * KSS;
        float s[8][4];
        #pragma unroll
        for (int j = 0; j < 8; j++)
            #pragma unroll
            for (int r = 0; r < 4; r++) s[j][r] = 0.f;
        #pragma unroll
        for (int kc = 0; kc < 8; kc++) {
            #pragma unroll
            for (int j = 0; j < 8; j++) {
                unsigned bf[2];
                bf[0] = *(const unsigned*)&Kb[(j * 8 + g) * KSS + kc * 8 + t4    ];
                bf[1] = *(const unsigned*)&Kb[(j * 8 + g) * KSS + kc * 8 + t4 + 4];
                mma_tf32(s[j], qf[kc], bf);
            }
        }

        // ---- mask tail columns ----
        const int lim = SEQ - kv0;
        if (lim < KT) {
            #pragma unroll
            for (int j = 0; j < 8; j++) {
                int c = j * 8 + 2 * t4;
                if (c     >= lim) { s[j][0] = -1e30f; s[j][2] = -1e30f; }
                if (c + 1 >= lim) { s[j][1] = -1e30f; s[j][3] = -1e30f; }
            }
        }

        // ---- online softmax (rows g and g+8, warp-local) ----
        float mx0 = -1e30f, mx1 = -1e30f;
        #pragma unroll
        for (int j = 0; j < 8; j++) {
            mx0 = fmaxf(mx0, fmaxf(s[j][0], s[j][1]));
            mx1 = fmaxf(mx1, fmaxf(s[j][2], s[j][3]));
        }
        mx0 = fmaxf(mx0, __shfl_xor_sync(0xffffffffu, mx0, 1));
        mx0 = fmaxf(mx0, __shfl_xor_sync(0xffffffffu, mx0, 2));
        mx1 = fmaxf(mx1, __shfl_xor_sync(0xffffffffu, mx1, 1));
        mx1 = fmaxf(mx1, __shfl_xor_sync(0xffffffffu, mx1, 2));

        float mn0 = fmaxf(m0, mx0), mn1 = fmaxf(m1, mx1);
        float a0 = __expf(m0 - mn0), a1 = __expf(m1 - mn1);
        m0 = mn0; m1 = mn1;

        float rs0 = 0.f, rs1 = 0.f;
        #pragma unroll
        for (int j = 0; j < 8; j++) {
            s[j][0] = __expf(s[j][0] - m0);
            s[j][1] = __expf(s[j][1] - m0);
            s[j][2] = __expf(s[j][2] - m1);
            s[j][3] = __expf(s[j][3] - m1);
            rs0 += s[j][0] + s[j][1];
            rs1 += s[j][2] + s[j][3];
        }
        rs0 += __shfl_xor_sync(0xffffffffu, rs0, 1);
        rs0 += __shfl_xor_sync(0xffffffffu, rs0, 2);
        rs1 += __shfl_xor_sync(0xffffffffu, rs1, 1);
        rs1 += __shfl_xor_sync(0xffffffffu, rs1, 2);
        l0 = l0 * a0 + rs0;
        l1 = l1 * a1 + rs1;

        // rescale O, write P (tf32 bits) to warp-private smem
        const int r0 = w * 16 + g;
        #pragma unroll
        for (int j = 0; j < 8; j++) {
            o[j][0] *= a0; o[j][1] *= a0; o[j][2] *= a1; o[j][3] *= a1;
            uint2 p01 = make_uint2(f2tf(s[j][0]), f2tf(s[j][1]));
            uint2 p23 = make_uint2(f2tf(s[j][2]), f2tf(s[j][3]));
            *(uint2*)&Psu[(r0    ) * KSS + j * 8 + 2 * t4] = p01;
            *(uint2*)&Psu[(r0 + 8) * KSS + j * 8 + 2 * t4] = p23;
        }
        __syncwarp();

        // ---- O += P V ----
        const float* Vb = Vsm + buf * 64 * VSS;
        #pragma unroll
        for (int kc = 0; kc < 8; kc++) {
            unsigned au[4];
            au[0] = Psu[(r0    ) * KSS + kc * 8 + t4    ];
            au[1] = Psu[(r0 + 8) * KSS + kc * 8 + t4    ];
            au[2] = Psu[(r0    ) * KSS + kc * 8 + t4 + 4];
            au[3] = Psu[(r0 + 8) * KSS + kc * 8 + t4 + 4];
            #pragma unroll
            for (int j = 0; j < 8; j++) {
                unsigned bf[2];
                bf[0] = *(const unsigned*)&Vb[(kc * 8 + t4    ) * VSS + j * 8 + g];
                bf[1] = *(const unsigned*)&Vb[(kc * 8 + t4 + 4) * VSS + j * 8 + g];
                mma_tf32(o[j], au, bf);
            }
        }

        if (it + 1 < NIT) {
            asm volatile("cp.async.wait_group 0;");
            __syncthreads();
            int nb = buf ^ 1;
            #pragma unroll
            for (int i = 0; i < 16; i++) {
                int id = t + i * 256;
                int r = id >> 6, c = id & 63;
                float* pk = &Ksm[(nb * 64 + r) * KSS + c];
                *(unsigned*)pk = f2tf(*pk);
                float* pv = &Vsm[(nb * 64 + r) * VSS + c];
                *(unsigned*)pv = f2tf(*pv);
            }
            __syncthreads();
        }
    }

    // ---- epilogue: normalize and store bf16 ----
    float inv0 = 1.f / l0, inv1 = 1.f / l1;
    int row0 = q0 + w * 16 + g;
    int row1 = row0 + 8;
    #pragma unroll
    for (int j = 0; j < 8; j++) {
        int col = j * 8 + 2 * t4;
        if (row0 < SEQ)
            *(__nv_bfloat162*)(out + ((size_t)b * SEQ + row0) * HID + h * HDIM + col) =
                __floats2bfloat162_rn(o[j][0] * inv0, o[j][1] * inv0);
        if (row1 < SEQ)
            *(__nv_bfloat162*)(out + ((size_t)b * SEQ + row1) * HID + h * HDIM + col) =
                __floats2bfloat162_rn(o[j][2] * inv1, o[j][3] * inv1);
    }
}

// ---------------------------------------------------------------------------
extern "C" void kernel_launch(void* const* d_in, const int* in_sizes, int n_in,
                              void* d_out, int out_size) {
    const float* hidden = (const float*)d_in[0];
    const float* n1g    = (const float*)d_in[1];
    const float* n1b    = (const float*)d_in[2];
    const float* qkvw   = (const float*)d_in[3];
    const float* qkvb   = (const float*)d_in[4];
    const float* projw  = (const float*)d_in[5];
    const float* projb  = (const float*)d_in[6];
    const float* ls1    = (const float*)d_in[7];
    const float* n2g    = (const float*)d_in[8];
    const float* n2b    = (const float*)d_in[9];
    const float* fc1w   = (const float*)d_in[10];
    const float* fc1b   = (const float*)d_in[11];
    const float* fc2w   = (const float*)d_in[12];
    const float* fc2b   = (const float*)d_in[13];
    const float* ls2    = (const float*)d_in[14];
    float* out = (float*)d_out;

    __nv_bfloat16 *xnorm, *attn, *mlp, *qkvw_bf, *projw_bf, *fc1w_bf, *fc2w_bf;
    float *qkv;
    cudaGetSymbolAddress((void**)&xnorm,    g_xnorm);
    cudaGetSymbolAddress((void**)&qkv,      g_qkv);
    cudaGetSymbolAddress((void**)&attn,     g_attn);
    cudaGetSymbolAddress((void**)&mlp,      g_mlp);
    cudaGetSymbolAddress((void**)&qkvw_bf,  g_qkvw);
    cudaGetSymbolAddress((void**)&projw_bf, g_projw);
    cudaGetSymbolAddress((void**)&fc1w_bf,  g_fc1w);
    cudaGetSymbolAddress((void**)&fc2w_bf,  g_fc2w);

    cudaFuncSetAttribute(flash_attn, cudaFuncAttributeMaxDynamicSharedMemorySize,
                         SM_TOT);

    const int MT = (M_TOK + 127) / 128;  // 129
    const int QT = (SEQ + 127) / 128;    // 9

    // 0. weight conversion fp32 -> bf16
    {
        int n;
        n = 3 * HID * HID / 4; f2bf_k<<<(n + 255) / 256, 256>>>(qkvw, qkvw_bf, n);
        n = HID * HID / 4;     f2bf_k<<<(n + 255) / 256, 256>>>(projw, projw_bf, n);
        n = IMED * HID / 4;    f2bf_k<<<(n + 255) / 256, 256>>>(fc1w, fc1w_bf, n);
        n = HID * IMED / 4;    f2bf_k<<<(n + 255) / 256, 256>>>(fc2w, fc2w_bf, n);
    }

    // 1. LN1 -> bf16
    layernorm_k<<<M_TOK, 256>>>(hidden, n1g, n1b, xnorm);
    // 2. QKV (bf16 x bf16 -> fp32)
    gemm_bf16<1><<<dim3(3 * HID / 128, MT), 256>>>(xnorm, qkvw_bf, qkvb, nullptr,
                                                   nullptr, qkv, nullptr,
                                                   M_TOK, 3 * HID, HID);
    // 3-5. fused attention (fp32 in, bf16 out)
    flash_attn<<<dim3(QT, BATCH * NHEADS), 256, SM_TOT>>>(qkv, attn);
    // 6. proj + ls1 residual -> d_out (fp32)
    gemm_bf16<3><<<dim3(HID / 128, MT), 256>>>(attn, projw_bf, projb, ls1, hidden,
                                               out, nullptr, M_TOK, HID, HID);
    // 7. LN2 -> bf16
    layernorm_k<<<M_TOK, 256>>>(out, n2g, n2b, xnorm);
    // 8. fc1 + gelu -> bf16
    gemm_bf16<2><<<dim3(IMED / 128, MT), 256>>>(xnorm, fc1w_bf, fc1b, nullptr,
                                                nullptr, nullptr, mlp,
                                                M_TOK, IMED, HID);
    // 9. fc2 + ls2 residual -> d_out (fp32, in place)
    gemm_bf16<3><<<dim3(HID / 128, MT), 256>>>(mlp, fc2w_bf, fc2b, ls2, out,
                                               out, nullptr, M_TOK, HID, IMED);
}